// round 5
// baseline (speedup 1.0000x reference)
#include <cuda_runtime.h>
#include <math.h>

#define BATCH 2
#define SEQ   2048
#define EMB   1024
#define NH    16
#define HD    64
#define QKV3  3072   // 3 * NH * HD
#define MROWS (BATCH * SEQ)   // 4096

// Scratch buffers (allocation-free: __device__ globals, zero-init at load)
__device__ float g_qkv[(size_t)BATCH * SEQ * QKV3];  // [b, s, {q,k,v}, h, d]
__device__ float g_att[(size_t)BATCH * SEQ * EMB];   // [b*s, h*d]

// ---------------------------------------------------------------------------
// SGEMM: C[M,N] = A[M,K] @ B[K,N], row-major, fp32.
// BM=BN=128, BK=8, 256 threads, 8x8 micro-tile. Requires M%128==0, N%128==0, K%8==0.
// ---------------------------------------------------------------------------
__global__ __launch_bounds__(256) void sgemm_kernel(
    const float* __restrict__ A, const float* __restrict__ B,
    float* __restrict__ C, int M, int N, int K)
{
    __shared__ float As[8][128];   // transposed A tile: As[k][m]
    __shared__ float Bs[8][128];   // Bs[k][n]

    const int tid = threadIdx.x;
    const int tx  = tid & 15;      // 0..15 -> n micro
    const int ty  = tid >> 4;      // 0..15 -> m micro
    const int bm  = blockIdx.y * 128;
    const int bn  = blockIdx.x * 128;

    // load mapping: A tile 128x8 (1 float4/thread), B tile 8x128 (1 float4/thread)
    const int ar = tid >> 1;            // 0..127
    const int ac = (tid & 1) * 4;       // 0 or 4
    const int br = tid >> 5;            // 0..7
    const int bc = (tid & 31) * 4;      // 0..124

    const float* Aptr = A + (size_t)(bm + ar) * K + ac;
    const float* Bptr = B + (size_t)br * N + bn + bc;

    float acc[8][8];
    #pragma unroll
    for (int i = 0; i < 8; i++)
        #pragma unroll
        for (int j = 0; j < 8; j++) acc[i][j] = 0.0f;

    for (int k0 = 0; k0 < K; k0 += 8) {
        float4 av = *(const float4*)(Aptr + k0);
        float4 bv = *(const float4*)(Bptr + (size_t)k0 * N);
        As[ac + 0][ar] = av.x; As[ac + 1][ar] = av.y;
        As[ac + 2][ar] = av.z; As[ac + 3][ar] = av.w;
        *(float4*)&Bs[br][bc] = bv;
        __syncthreads();

        #pragma unroll
        for (int k = 0; k < 8; k++) {
            float a[8], b[8];
            *(float4*)&a[0] = *(float4*)&As[k][ty * 8];
            *(float4*)&a[4] = *(float4*)&As[k][ty * 8 + 4];
            *(float4*)&b[0] = *(float4*)&Bs[k][tx * 8];
            *(float4*)&b[4] = *(float4*)&Bs[k][tx * 8 + 4];
            #pragma unroll
            for (int i = 0; i < 8; i++)
                #pragma unroll
                for (int j = 0; j < 8; j++)
                    acc[i][j] = fmaf(a[i], b[j], acc[i][j]);
        }
        __syncthreads();
    }

    #pragma unroll
    for (int i = 0; i < 8; i++) {
        float* cp = C + (size_t)(bm + ty * 8 + i) * N + bn + tx * 8;
        *(float4*)cp       = make_float4(acc[i][0], acc[i][1], acc[i][2], acc[i][3]);
        *(float4*)(cp + 4) = make_float4(acc[i][4], acc[i][5], acc[i][6], acc[i][7]);
    }
}

// ---------------------------------------------------------------------------
// RoPE applied in place to the q and k slices of g_qkv.
// One thread per (b, s, h, pair); pair in [0,32).
// ---------------------------------------------------------------------------
__global__ __launch_bounds__(256) void rope_kernel(float* __restrict__ qkv)
{
    int idx = blockIdx.x * 256 + threadIdx.x;      // total = 2*2048*16*32 = 2097152
    int pair = idx & 31;
    int h    = (idx >> 5) & 15;
    int s    = (idx >> 9) & 2047;
    int b    = idx >> 20;

    float expo = (float)(2 * pair) * (1.0f / 64.0f);
    float freq = powf(10000.0f, -expo);
    float ang  = (float)s * freq;
    float sn, cs;
    sincosf(ang, &sn, &cs);

    size_t base = ((size_t)(b * SEQ + s)) * QKV3 + h * HD + 2 * pair;
    // q
    float x1 = qkv[base], x2 = qkv[base + 1];
    qkv[base]     = x1 * cs - x2 * sn;
    qkv[base + 1] = x1 * sn + x2 * cs;
    // k
    x1 = qkv[base + EMB]; x2 = qkv[base + EMB + 1];
    qkv[base + EMB]     = x1 * cs - x2 * sn;
    qkv[base + EMB + 1] = x1 * sn + x2 * cs;
}

// ---------------------------------------------------------------------------
// Flash attention (fp32, causal). Block = 128 threads, tile 64 q-rows x 64 kv.
// Thread (tx in [0,8), ty in [0,16)) owns rows ty*4..ty*4+3, cols tx*8..tx*8+7.
// smem = exactly 48KB: Qt[d][r], KP (K^T then P^T), Vs[j][d].
// ---------------------------------------------------------------------------
__global__ __launch_bounds__(128) void attn_kernel(
    const float* __restrict__ qkv, float* __restrict__ out)
{
    __shared__ float Qt[HD][64];    // Qt[d][r]
    __shared__ float KP[64][64];    // phase 1: Kt[d][j]; phase 2: Pt[j][r]
    __shared__ float Vs[64][64];    // Vs[j][d]

    const int tid = threadIdx.x;
    const int tx  = tid & 7;
    const int ty  = tid >> 3;
    const int qt  = blockIdx.x;     // 0..31
    const int h   = blockIdx.y;
    const int b   = blockIdx.z;
    const int q0  = qt * 64;

    const float* qbase = qkv + (size_t)b * SEQ * QKV3 + h * HD;
    const float* kbase = qbase + EMB;
    const float* vbase = qbase + 2 * EMB;

    // Load Q tile transposed: Qt[d][r]
    for (int idx = tid; idx < 64 * 16; idx += 128) {
        int r  = idx >> 4;
        int c4 = (idx & 15) * 4;
        float4 v = *(const float4*)(qbase + (size_t)(q0 + r) * QKV3 + c4);
        Qt[c4 + 0][r] = v.x; Qt[c4 + 1][r] = v.y;
        Qt[c4 + 2][r] = v.z; Qt[c4 + 3][r] = v.w;
    }

    float m_r[4], l_r[4], o_acc[4][8];
    #pragma unroll
    for (int i = 0; i < 4; i++) {
        m_r[i] = -1e30f; l_r[i] = 0.0f;
        #pragma unroll
        for (int jj = 0; jj < 8; jj++) o_acc[i][jj] = 0.0f;
    }

    for (int kt = 0; kt <= qt; kt++) {
        const int k0 = kt * 64;
        __syncthreads();   // previous iteration's P/V reads (and Q load) done

        // Load K tile transposed into KP, V tile row-major into Vs
        for (int idx = tid; idx < 64 * 16; idx += 128) {
            int r  = idx >> 4;
            int c4 = (idx & 15) * 4;
            float4 v = *(const float4*)(kbase + (size_t)(k0 + r) * QKV3 + c4);
            KP[c4 + 0][r] = v.x; KP[c4 + 1][r] = v.y;
            KP[c4 + 2][r] = v.z; KP[c4 + 3][r] = v.w;
            float4 w = *(const float4*)(vbase + (size_t)(k0 + r) * QKV3 + c4);
            *(float4*)&Vs[r][c4] = w;
        }
        __syncthreads();

        // S = Q @ K^T over d (4x8 micro-tile per thread)
        float s_acc[4][8];
        #pragma unroll
        for (int i = 0; i < 4; i++)
            #pragma unroll
            for (int jj = 0; jj < 8; jj++) s_acc[i][jj] = 0.0f;

        #pragma unroll 8
        for (int d = 0; d < HD; d++) {
            float4 qv  = *(float4*)&Qt[d][ty * 4];
            float4 kv0 = *(float4*)&KP[d][tx * 8];
            float4 kv1 = *(float4*)&KP[d][tx * 8 + 4];
            float qa[4] = {qv.x, qv.y, qv.z, qv.w};
            float ka[8] = {kv0.x, kv0.y, kv0.z, kv0.w, kv1.x, kv1.y, kv1.z, kv1.w};
            #pragma unroll
            for (int i = 0; i < 4; i++)
                #pragma unroll
                for (int jj = 0; jj < 8; jj++)
                    s_acc[i][jj] = fmaf(qa[i], ka[jj], s_acc[i][jj]);
        }

        // Online softmax per row (8 lanes per row-group are contiguous in warp)
        #pragma unroll
        for (int i = 0; i < 4; i++) {
            const int qrow = q0 + ty * 4 + i;
            float mx = -1e30f;
            #pragma unroll
            for (int jj = 0; jj < 8; jj++) {
                int kc = k0 + tx * 8 + jj;
                float sv = s_acc[i][jj] * 0.125f;       // 1/sqrt(64)
                if (kc > qrow) sv = -1e9f;              // NEG_INF
                s_acc[i][jj] = sv;
                mx = fmaxf(mx, sv);
            }
            mx = fmaxf(mx, __shfl_xor_sync(0xffffffffu, mx, 1));
            mx = fmaxf(mx, __shfl_xor_sync(0xffffffffu, mx, 2));
            mx = fmaxf(mx, __shfl_xor_sync(0xffffffffu, mx, 4));
            float mnew = fmaxf(m_r[i], mx);
            float corr = __expf(m_r[i] - mnew);
            m_r[i] = mnew;
            float rs = 0.0f;
            #pragma unroll
            for (int jj = 0; jj < 8; jj++) {
                float p = __expf(s_acc[i][jj] - mnew);
                s_acc[i][jj] = p;
                rs += p;
            }
            rs += __shfl_xor_sync(0xffffffffu, rs, 1);
            rs += __shfl_xor_sync(0xffffffffu, rs, 2);
            rs += __shfl_xor_sync(0xffffffffu, rs, 4);
            l_r[i] = l_r[i] * corr + rs;
            #pragma unroll
            for (int jj = 0; jj < 8; jj++) o_acc[i][jj] *= corr;
        }

        __syncthreads();   // everyone done reading Kt
        // Write P transposed: Pt[j][r] into KP
        #pragma unroll
        for (int jj = 0; jj < 8; jj++) {
            float4 pv = make_float4(s_acc[0][jj], s_acc[1][jj], s_acc[2][jj], s_acc[3][jj]);
            *(float4*)&KP[tx * 8 + jj][ty * 4] = pv;
        }
        __syncthreads();

        // O += P @ V
        #pragma unroll 8
        for (int j = 0; j < 64; j++) {
            float4 pv = *(float4*)&KP[j][ty * 4];
            float4 v0 = *(float4*)&Vs[j][tx * 8];
            float4 v1 = *(float4*)&Vs[j][tx * 8 + 4];
            float pa[4] = {pv.x, pv.y, pv.z, pv.w};
            float va[8] = {v0.x, v0.y, v0.z, v0.w, v1.x, v1.y, v1.z, v1.w};
            #pragma unroll
            for (int i = 0; i < 4; i++)
                #pragma unroll
                for (int jj = 0; jj < 8; jj++)
                    o_acc[i][jj] = fmaf(pa[i], va[jj], o_acc[i][jj]);
        }
    }

    // Epilogue: normalize and store to att buffer [b*s, h*d]
    #pragma unroll
    for (int i = 0; i < 4; i++) {
        float inv = 1.0f / l_r[i];
        int row = q0 + ty * 4 + i;
        float* op = out + ((size_t)b * SEQ + row) * EMB + h * HD + tx * 8;
        *(float4*)op = make_float4(o_acc[i][0] * inv, o_acc[i][1] * inv,
                                   o_acc[i][2] * inv, o_acc[i][3] * inv);
        *(float4*)(op + 4) = make_float4(o_acc[i][4] * inv, o_acc[i][5] * inv,
                                         o_acc[i][6] * inv, o_acc[i][7] * inv);
    }
}

// ---------------------------------------------------------------------------
extern "C" void kernel_launch(void* const* d_in, const int* in_sizes, int n_in,
                              void* d_out, int out_size)
{
    const float* x    = (const float*)d_in[0];   // [2,2048,1024]
    const float* Wqkv = (const float*)d_in[1];   // [1024,3072]
    const float* Wout = (const float*)d_in[2];   // [1024,1024]
    float* out        = (float*)d_out;           // [2,2048,1024]

    float* qkv = nullptr;
    float* att = nullptr;
    cudaGetSymbolAddress((void**)&qkv, g_qkv);
    cudaGetSymbolAddress((void**)&att, g_att);

    // 1) QKV projection: [4096,1024] @ [1024,3072]
    {
        dim3 grid(QKV3 / 128, MROWS / 128);
        sgemm_kernel<<<grid, 256>>>(x, Wqkv, qkv, MROWS, QKV3, EMB);
    }
    // 2) RoPE on q,k
    rope_kernel<<<(BATCH * SEQ * NH * 32) / 256, 256>>>(qkv);
    // 3) Causal flash attention
    {
        dim3 grid(SEQ / 64, NH, BATCH);
        attn_kernel<<<grid, 128>>>(qkv, att);
    }
    // 4) Output projection: [4096,1024] @ [1024,1024]
    {
        dim3 grid(EMB / 128, MROWS / 128);
        sgemm_kernel<<<grid, 256>>>(att, Wout, out, MROWS, EMB, EMB);
    }
}

// round 6
// speedup vs baseline: 3.9416x; 3.9416x over previous
#include <cuda_runtime.h>
#include <math.h>

#define BATCH 2
#define SEQ   2048
#define EMB   1024
#define NH    16
#define HD    64
#define QKV3  3072   // 3 * NH * HD
#define MROWS (BATCH * SEQ)   // 4096

// Scratch (allocation-free: __device__ globals)
__device__ float g_qkv[(size_t)BATCH * SEQ * QKV3];  // [b, s, {q,k,v}, h, d]
__device__ float g_att[(size_t)BATCH * SEQ * EMB];   // [b*s, h*d]

// ---------------------------------------------------------------------------
// tf32 helpers
// ---------------------------------------------------------------------------
__device__ __forceinline__ unsigned f2tf(float x) {
    unsigned u;
    asm("cvt.rna.tf32.f32 %0, %1;" : "=r"(u) : "f"(x));
    return u;
}

// D += A*B, m16n8k8, A row-major, B col-major, tf32 in / f32 accum.
__device__ __forceinline__ void mma8(float* c, const unsigned* a, const unsigned* b) {
    asm volatile(
        "mma.sync.aligned.m16n8k8.row.col.f32.tf32.tf32.f32 "
        "{%0,%1,%2,%3}, {%4,%5,%6,%7}, {%8,%9}, {%0,%1,%2,%3};"
        : "+f"(c[0]), "+f"(c[1]), "+f"(c[2]), "+f"(c[3])
        : "r"(a[0]), "r"(a[1]), "r"(a[2]), "r"(a[3]), "r"(b[0]), "r"(b[1]));
}

// ---------------------------------------------------------------------------
// tf32 tensor-core GEMM: C[M,N] = A[M,K] @ B[K,N], fp32 in/out.
// BM=128, BN=128, BK=32; 256 threads = 8 warps (4m x 2n), warp tile 32x64.
// tf32 conversion happens once at smem store. Pads chosen conflict-free:
//  As[r][k]: quad banks 4g+tg (pad 36);  Bs[k][n]: banks 8tg+g (pad 136).
// ---------------------------------------------------------------------------
#define GPA 36
#define GPB 136
__global__ __launch_bounds__(256, 2) void gemm_tf32(
    const float* __restrict__ A, const float* __restrict__ B,
    float* __restrict__ C, int M, int N, int K)
{
    __shared__ unsigned As[128][GPA];
    __shared__ unsigned Bs[32][GPB];

    const int tid  = threadIdx.x;
    const int lane = tid & 31;
    const int warp = tid >> 5;
    const int g    = lane >> 2;    // groupID 0..7
    const int tg   = lane & 3;     // thread-in-group 0..3
    const int wm   = warp >> 1;    // 0..3
    const int wn   = warp & 1;     // 0..1
    const int bm   = blockIdx.y * 128;
    const int bn   = blockIdx.x * 128;

    float acc[2][8][4];
    #pragma unroll
    for (int mf = 0; mf < 2; mf++)
        #pragma unroll
        for (int nf = 0; nf < 8; nf++)
            #pragma unroll
            for (int i = 0; i < 4; i++) acc[mf][nf][i] = 0.0f;

    for (int k0 = 0; k0 < K; k0 += 32) {
        // Load + convert tiles: A 128x32, B 32x128 (4 float4 chunks each/thread)
        #pragma unroll
        for (int t = 0; t < 4; t++) {
            int ch = tid + t * 256;
            int ar = ch >> 3, ac = (ch & 7) * 4;
            float4 av = *(const float4*)(A + (size_t)(bm + ar) * K + k0 + ac);
            *(uint4*)&As[ar][ac] =
                make_uint4(f2tf(av.x), f2tf(av.y), f2tf(av.z), f2tf(av.w));
            int br = ch >> 5, bc = (ch & 31) * 4;
            float4 bv = *(const float4*)(B + (size_t)(k0 + br) * N + bn + bc);
            *(uint4*)&Bs[br][bc] =
                make_uint4(f2tf(bv.x), f2tf(bv.y), f2tf(bv.z), f2tf(bv.w));
        }
        __syncthreads();

        #pragma unroll
        for (int ks = 0; ks < 4; ks++) {
            unsigned a[2][4];
            #pragma unroll
            for (int mf = 0; mf < 2; mf++) {
                int r = wm * 32 + mf * 16;
                a[mf][0] = As[r + g    ][ks * 8 + tg];
                a[mf][1] = As[r + g + 8][ks * 8 + tg];
                a[mf][2] = As[r + g    ][ks * 8 + tg + 4];
                a[mf][3] = As[r + g + 8][ks * 8 + tg + 4];
            }
            #pragma unroll
            for (int nf = 0; nf < 8; nf++) {
                unsigned bb[2];
                int c = wn * 64 + nf * 8 + g;
                bb[0] = Bs[ks * 8 + tg    ][c];
                bb[1] = Bs[ks * 8 + tg + 4][c];
                mma8(acc[0][nf], a[0], bb);
                mma8(acc[1][nf], a[1], bb);
            }
        }
        __syncthreads();
    }

    // Epilogue: accum layout c0:(g,2tg) c1:(g,2tg+1) c2:(g+8,2tg) c3:(g+8,2tg+1)
    #pragma unroll
    for (int mf = 0; mf < 2; mf++)
        #pragma unroll
        for (int nf = 0; nf < 8; nf++) {
            int row = bm + wm * 32 + mf * 16 + g;
            int col = bn + wn * 64 + nf * 8 + 2 * tg;
            *(float2*)(C + (size_t)row * N + col) =
                make_float2(acc[mf][nf][0], acc[mf][nf][1]);
            *(float2*)(C + (size_t)(row + 8) * N + col) =
                make_float2(acc[mf][nf][2], acc[mf][nf][3]);
        }
}

// ---------------------------------------------------------------------------
// RoPE in place on q,k slices of g_qkv. One thread per (b,s,h,pair).
// ---------------------------------------------------------------------------
__global__ __launch_bounds__(256) void rope_kernel(float* __restrict__ qkv)
{
    int idx  = blockIdx.x * 256 + threadIdx.x;
    int pair = idx & 31;
    int h    = (idx >> 5) & 15;
    int s    = (idx >> 9) & 2047;
    int b    = idx >> 20;

    float expo = (float)(2 * pair) * (1.0f / 64.0f);
    float freq = powf(10000.0f, -expo);
    float ang  = (float)s * freq;
    float sn, cs;
    sincosf(ang, &sn, &cs);

    size_t base = ((size_t)(b * SEQ + s)) * QKV3 + h * HD + 2 * pair;
    float x1 = qkv[base], x2 = qkv[base + 1];
    qkv[base]     = x1 * cs - x2 * sn;
    qkv[base + 1] = x1 * sn + x2 * cs;
    x1 = qkv[base + EMB]; x2 = qkv[base + EMB + 1];
    qkv[base + EMB]     = x1 * cs - x2 * sn;
    qkv[base + EMB + 1] = x1 * sn + x2 * cs;
}

// ---------------------------------------------------------------------------
// Flash attention, tf32 tensor cores. Block = 128 threads (4 warps), tile
// 64 q-rows x 64 kv. Warp w owns q-rows w*16..w*16+15 (one m16 fragment row).
// Q fragments register-resident (loaded once, scale 1/8 folded in).
// KP buffer is K^ [kv][d] during S phase, then reused for P [qrow][kv].
// Pads: KP 68 (banks 4g+tg for [n][k] and [m][k] reads), Vs 72 (banks 8tg+g).
// ---------------------------------------------------------------------------
__global__ __launch_bounds__(128, 3) void attn_mma(
    const float* __restrict__ qkv, float* __restrict__ out)
{
    __shared__ unsigned KP[64][68];
    __shared__ unsigned Vs[64][72];

    const int tid  = threadIdx.x;
    const int lane = tid & 31;
    const int warp = tid >> 5;
    const int g    = lane >> 2;
    const int tg   = lane & 3;
    const int qt   = blockIdx.x;    // 0..31
    const int h    = blockIdx.y;
    const int b    = blockIdx.z;
    const int q0   = qt * 64;
    const int m0   = warp * 16;

    const float* qb = qkv + (size_t)b * SEQ * QKV3 + h * HD;
    const float* kb = qb + EMB;
    const float* vb = qb + 2 * EMB;

    // Q fragments for this warp's 16 rows, all 8 k-steps (d = 0..63).
    unsigned qa[8][4];
    #pragma unroll
    for (int ks = 0; ks < 8; ks++) {
        const float* r0p = qb + (size_t)(q0 + m0 + g) * QKV3 + ks * 8 + tg;
        const float* r1p = r0p + (size_t)8 * QKV3;
        qa[ks][0] = f2tf(0.125f * r0p[0]);
        qa[ks][1] = f2tf(0.125f * r1p[0]);
        qa[ks][2] = f2tf(0.125f * r0p[4]);
        qa[ks][3] = f2tf(0.125f * r1p[4]);
    }

    float m_r[2] = {-1e30f, -1e30f};
    float l_r[2] = {0.0f, 0.0f};
    float o[8][4];
    #pragma unroll
    for (int nf = 0; nf < 8; nf++)
        #pragma unroll
        for (int i = 0; i < 4; i++) o[nf][i] = 0.0f;

    for (int kt = 0; kt <= qt; kt++) {
        const int k0 = kt * 64;
        __syncthreads();   // prior PV fragment reads finished

        // Load + convert K,V tiles (row = kv pos, col = d)
        for (int idx = tid; idx < 64 * 16; idx += 128) {
            int r = idx >> 4, c4 = (idx & 15) * 4;
            float4 kv4 = *(const float4*)(kb + (size_t)(k0 + r) * QKV3 + c4);
            *(uint4*)&KP[r][c4] =
                make_uint4(f2tf(kv4.x), f2tf(kv4.y), f2tf(kv4.z), f2tf(kv4.w));
            float4 vv4 = *(const float4*)(vb + (size_t)(k0 + r) * QKV3 + c4);
            *(uint4*)&Vs[r][c4] =
                make_uint4(f2tf(vv4.x), f2tf(vv4.y), f2tf(vv4.z), f2tf(vv4.w));
        }
        __syncthreads();

        // S = (Q/8) @ K^T : 8 n-frags over kv, f32 accum
        float s[8][4];
        #pragma unroll
        for (int nf = 0; nf < 8; nf++)
            #pragma unroll
            for (int i = 0; i < 4; i++) s[nf][i] = 0.0f;

        #pragma unroll
        for (int ks = 0; ks < 8; ks++) {
            #pragma unroll
            for (int nf = 0; nf < 8; nf++) {
                unsigned bb[2];
                bb[0] = KP[nf * 8 + g][ks * 8 + tg];      // B[k=d][n=kv] = K[kv][d]
                bb[1] = KP[nf * 8 + g][ks * 8 + tg + 4];
                mma8(s[nf], qa[ks], bb);
            }
        }

        // Causal mask (only the diagonal tile needs it; k0 == q0 there)
        if (kt == qt) {
            #pragma unroll
            for (int nf = 0; nf < 8; nf++) {
                int col = nf * 8 + 2 * tg;
                int r0 = m0 + g, r1 = r0 + 8;
                if (col     > r0) s[nf][0] = -1e9f;
                if (col + 1 > r0) s[nf][1] = -1e9f;
                if (col     > r1) s[nf][2] = -1e9f;
                if (col + 1 > r1) s[nf][3] = -1e9f;
            }
        }

        // Online softmax (rows: i=0 -> g, i=1 -> g+8; reduce over tg via xor 1,2)
        #pragma unroll
        for (int i = 0; i < 2; i++) {
            float mx = -1e30f;
            #pragma unroll
            for (int nf = 0; nf < 8; nf++)
                mx = fmaxf(mx, fmaxf(s[nf][2 * i], s[nf][2 * i + 1]));
            mx = fmaxf(mx, __shfl_xor_sync(0xffffffffu, mx, 1));
            mx = fmaxf(mx, __shfl_xor_sync(0xffffffffu, mx, 2));
            float mn   = fmaxf(m_r[i], mx);
            float corr = __expf(m_r[i] - mn);
            m_r[i] = mn;
            float rs = 0.0f;
            #pragma unroll
            for (int nf = 0; nf < 8; nf++) {
                float p0 = __expf(s[nf][2 * i]     - mn);
                float p1 = __expf(s[nf][2 * i + 1] - mn);
                s[nf][2 * i] = p0; s[nf][2 * i + 1] = p1;
                rs += p0 + p1;
            }
            rs += __shfl_xor_sync(0xffffffffu, rs, 1);
            rs += __shfl_xor_sync(0xffffffffu, rs, 2);
            l_r[i] = l_r[i] * corr + rs;
            #pragma unroll
            for (int nf = 0; nf < 8; nf++) {
                o[nf][2 * i]     *= corr;
                o[nf][2 * i + 1] *= corr;
            }
        }

        __syncthreads();   // all warps done reading KP as K
        // Write P [qrow_local][kv_local] into KP (tf32 bits)
        #pragma unroll
        for (int nf = 0; nf < 8; nf++) {
            int col = nf * 8 + 2 * tg;
            *(uint2*)&KP[m0 + g    ][col] = make_uint2(f2tf(s[nf][0]), f2tf(s[nf][1]));
            *(uint2*)&KP[m0 + g + 8][col] = make_uint2(f2tf(s[nf][2]), f2tf(s[nf][3]));
        }
        __syncthreads();

        // O += P @ V
        #pragma unroll
        for (int ks = 0; ks < 8; ks++) {
            unsigned pa[4];
            pa[0] = KP[m0 + g    ][ks * 8 + tg];
            pa[1] = KP[m0 + g + 8][ks * 8 + tg];
            pa[2] = KP[m0 + g    ][ks * 8 + tg + 4];
            pa[3] = KP[m0 + g + 8][ks * 8 + tg + 4];
            #pragma unroll
            for (int nf = 0; nf < 8; nf++) {
                unsigned bb[2];
                bb[0] = Vs[ks * 8 + tg    ][nf * 8 + g];  // B[k=kv][n=d] = V[kv][d]
                bb[1] = Vs[ks * 8 + tg + 4][nf * 8 + g];
                mma8(o[nf], pa, bb);
            }
        }
    }

    // Epilogue: normalize, store to att buffer [b*s, h*d]
    #pragma unroll
    for (int i = 0; i < 2; i++) {
        float inv = 1.0f / l_r[i];
        int row = q0 + m0 + g + 8 * i;
        float* op = out + ((size_t)b * SEQ + row) * EMB + h * HD;
        #pragma unroll
        for (int nf = 0; nf < 8; nf++) {
            int col = nf * 8 + 2 * tg;
            *(float2*)(op + col) =
                make_float2(o[nf][2 * i] * inv, o[nf][2 * i + 1] * inv);
        }
    }
}

// ---------------------------------------------------------------------------
extern "C" void kernel_launch(void* const* d_in, const int* in_sizes, int n_in,
                              void* d_out, int out_size)
{
    const float* x    = (const float*)d_in[0];   // [2,2048,1024]
    const float* Wqkv = (const float*)d_in[1];   // [1024,3072]
    const float* Wout = (const float*)d_in[2];   // [1024,1024]
    float* out        = (float*)d_out;           // [2,2048,1024]

    float* qkv = nullptr;
    float* att = nullptr;
    cudaGetSymbolAddress((void**)&qkv, g_qkv);
    cudaGetSymbolAddress((void**)&att, g_att);

    // 1) QKV projection: [4096,1024] @ [1024,3072]
    {
        dim3 grid(QKV3 / 128, MROWS / 128);
        gemm_tf32<<<grid, 256>>>(x, Wqkv, qkv, MROWS, QKV3, EMB);
    }
    // 2) RoPE on q,k
    rope_kernel<<<(BATCH * SEQ * NH * 32) / 256, 256>>>(qkv);
    // 3) Causal flash attention (tensor cores)
    {
        dim3 grid(SEQ / 64, NH, BATCH);
        attn_mma<<<grid, 128>>>(qkv, att);
    }
    // 4) Output projection: [4096,1024] @ [1024,1024]
    {
        dim3 grid(EMB / 128, MROWS / 128);
        gemm_tf32<<<grid, 256>>>(att, Wout, out, MROWS, EMB, EMB);
    }
}